// round 15
// baseline (speedup 1.0000x reference)
#include <cuda_runtime.h>
#include <cuda_bf16.h>
#include <cuda_fp16.h>
#include <cstdint>

#define NNODES 50000
#define NEDGES 600000

// ---------------- scratch (device globals) -------------------------------------
__device__ int   g_deg[NNODES];          // zero-init; re-zeroed by scan
__device__ int   g_rowoff[NNODES + 1];
__device__ int   g_woff[NNODES];
__device__ int   g_blkagg[64];
__device__ int   g_blkinc[64];
__device__ int   g_flag[64];             // lookback flags; reset by scatter
__device__ int2  g_edge[NEDGES];         // (src, w_bits)
__device__ float g_h[NNODES * 128];      // layer outputs fp32; layer2: [P|R]
__device__ __half g_x16[NNODES * 128];   // fp16 gather copy of x
__device__ __half g_h16[NNODES * 128];   // fp16 gather copy of h (per layer)
__device__ __nv_bfloat16 g_xH[NNODES * 128], g_xL[NNODES * 128];
__device__ __nv_bfloat16 g_mH[NNODES * 128], g_mL[NNODES * 128];
__device__ __nv_bfloat16 g_yH[NNODES * 128], g_yL[NNODES * 128];
__device__ __nv_bfloat16 g_BH[98304], g_BL[98304];   // W0 W1 W2, [n][k] stride 256
__device__ float g_statsA[512];          // layer0: [0,256) ; layer1: [256,512)

// ---------------- helpers ------------------------------------------------------
__device__ __forceinline__ uint32_t smem_u32(const void* p) {
    uint32_t a;
    asm("{ .reg .u64 t; cvta.to.shared.u64 t, %1; cvt.u32.u64 %0, t; }" : "=r"(a) : "l"(p));
    return a;
}
__device__ __forceinline__ void ldsm_x4(uint32_t addr, uint32_t r[4]) {
    asm volatile("ldmatrix.sync.aligned.m8n8.x4.shared.b16 {%0,%1,%2,%3}, [%4];"
        : "=r"(r[0]), "=r"(r[1]), "=r"(r[2]), "=r"(r[3]) : "r"(addr));
}
__device__ __forceinline__ void mma16816(float c[4], const uint32_t a[4], uint32_t b0, uint32_t b1) {
    asm volatile("mma.sync.aligned.m16n8k16.row.col.f32.bf16.bf16.f32 "
        "{%0,%1,%2,%3}, {%4,%5,%6,%7}, {%8,%9}, {%0,%1,%2,%3};"
        : "+f"(c[0]), "+f"(c[1]), "+f"(c[2]), "+f"(c[3])
        : "r"(a[0]), "r"(a[1]), "r"(a[2]), "r"(a[3]), "r"(b0), "r"(b1));
}
__device__ __forceinline__ void cpa16(uint32_t dst, const void* src, bool pred) {
    int sz = pred ? 16 : 0;
    asm volatile("cp.async.cg.shared.global [%0], [%1], 16, %2;"
        :: "r"(dst), "l"(src), "r"(sz) : "memory");
}
__device__ __forceinline__ void split2(float a, float b, uint32_t& hi, uint32_t& lo) {
    __nv_bfloat162 h = __floats2bfloat162_rn(a, b);
    float ha = __bfloat162float(h.x), hb = __bfloat162float(h.y);
    __nv_bfloat162 l = __floats2bfloat162_rn(a - ha, b - hb);
    hi = *reinterpret_cast<uint32_t*>(&h);
    lo = *reinterpret_cast<uint32_t*>(&l);
}
// BN coefficients from single-address raw stats
__device__ __forceinline__ void bn_coef(const float* __restrict__ stats,
                                        const float* __restrict__ gamma,
                                        const float* __restrict__ beta,
                                        float invM, int c, float& sc, float& sh) {
    float mu  = stats[c] * invM;
    float var = stats[128 + c] * invM - mu * mu;
    float g = gamma[c] * rsqrtf(var + 1e-5f);
    sc = g;
    sh = beta[c] - mu * g;
}

// ---------------- prep: x split + x16 + weights + degree count + stats zero ----
__global__ void prep_kernel(const float* __restrict__ x,
                            const int* __restrict__ dst,
                            const float* __restrict__ Wl0, const float* __restrict__ Wr0,
                            const float* __restrict__ Wl1, const float* __restrict__ Wr1,
                            const float* __restrict__ Wl2, const float* __restrict__ Wr2,
                            int n4, int E) {
    int gid = blockIdx.x * blockDim.x + threadIdx.x;
    if (gid < n4) {
        float4 v = ((const float4*)x)[gid];
        uint32_t h01, l01, h23, l23;
        split2(v.x, v.y, h01, l01);
        split2(v.z, v.w, h23, l23);
        ((uint2*)g_xH)[gid] = make_uint2(h01, h23);
        ((uint2*)g_xL)[gid] = make_uint2(l01, l23);
        __half2 p01 = __floats2half2_rn(v.x, v.y);
        __half2 p23 = __floats2half2_rn(v.z, v.w);
        uint2 u;
        u.x = *reinterpret_cast<uint32_t*>(&p01);
        u.y = *reinterpret_cast<uint32_t*>(&p23);
        ((uint2*)g_x16)[gid] = u;
    }
    if (gid < E) atomicAdd(&g_deg[dst[gid]], 1);
    if (gid < 512) g_statsA[gid] = 0.f;
    if (gid < 98304) {
        float v;
        int t;
        if (gid < 32768) {
            t = gid;
            int n = t >> 8, k = t & 255;
            v = (k < 128) ? Wl0[k * 128 + n] : Wr0[(k - 128) * 128 + n];
        } else if (gid < 65536) {
            t = gid - 32768;
            int n = t >> 8, k = t & 255;
            v = (k < 128) ? Wl1[k * 128 + n] : Wr1[(k - 128) * 128 + n];
        } else {
            t = gid - 65536;
            int n = t >> 8, k = t & 255;
            if (k < 128) v = (n < 64) ? Wl2[k * 64 + n] : Wr2[k * 64 + (n - 64)];
            else v = 0.f;
        }
        __nv_bfloat16 h = __float2bfloat16_rn(v);
        g_BH[gid] = h;
        g_BL[gid] = __float2bfloat16_rn(v - __bfloat162float(h));
    }
}

// ---------------- single-kernel decoupled-lookback scan -------------------------
__global__ void scan_kernel(int n) {
    const int b = blockIdx.x, tid = threadIdx.x;
    const int lane = tid & 31, wid = tid >> 5;
    int i = b * 1024 + tid;
    int v = (i < n) ? g_deg[i] : 0;
    int x = v;
    #pragma unroll
    for (int o = 1; o < 32; o <<= 1) {
        int t2 = __shfl_up_sync(0xFFFFFFFFu, x, o);
        if (lane >= o) x += t2;
    }
    __shared__ int ws[32];
    __shared__ int sh_base, sh_tot;
    if (lane == 31) ws[wid] = x;
    __syncthreads();
    if (wid == 0) {
        int y = ws[lane];
        #pragma unroll
        for (int o = 1; o < 32; o <<= 1) {
            int t2 = __shfl_up_sync(0xFFFFFFFFu, y, o);
            if (lane >= o) y += t2;
        }
        ws[lane] = y;
    }
    __syncthreads();
    const int S = ws[31];
    if (tid == 0) {
        g_blkagg[b] = S;
        __threadfence();
        atomicExch(&g_flag[b], 1);
        int excl = 0;
        for (int p = b - 1; p >= 0; ) {
            int f;
            do { f = atomicAdd(&g_flag[p], 0); } while (f == 0);
            __threadfence();
            if (f == 2) { excl += g_blkinc[p]; break; }
            excl += g_blkagg[p];
            p--;
        }
        g_blkinc[b] = excl + S;
        __threadfence();
        atomicExch(&g_flag[b], 2);
        sh_base = excl;
        sh_tot  = excl + S;
    }
    __syncthreads();
    int excl_i = x - v + (wid ? ws[wid - 1] : 0) + sh_base;
    if (i < n) {
        g_rowoff[i] = excl_i;
        g_woff[i]   = excl_i;
        g_deg[i]    = 0;
    }
    if (b == gridDim.x - 1 && tid == 0) g_rowoff[n] = sh_tot;
}

__global__ void scatter_kernel(const int* __restrict__ src, const int* __restrict__ dst,
                               const float* __restrict__ w, int e) {
    int i = blockIdx.x * blockDim.x + threadIdx.x;
    if (i < 64) g_flag[i] = 0;              // reset lookback flags for next replay
    if (i < e) {
        int d = dst[i];
        int p = atomicAdd(&g_woff[d], 1);
        g_edge[p] = make_int2(src[i], __float_as_int(w[i]));
    }
}

// ---------------- fused aggregate (+BN gather, fp16 source) & bnapply -----------
template <bool BN>
__global__ void __launch_bounds__(256)
layer_mid(const __half* __restrict__ X16,
          const float* __restrict__ stats,
          const float* __restrict__ gamma,
          const float* __restrict__ beta,
          float invM, int n, int nAgg) {
    __shared__ float s_sc[128], s_sh[128];
    int tid = threadIdx.x;
    if (BN) {
        if (tid < 128) {
            float a, b;
            bn_coef(stats, gamma, beta, invM, tid, a, b);
            s_sc[tid] = a;
            s_sh[tid] = b;
        }
        __syncthreads();
    }

    if ((int)blockIdx.x >= nAgg) {
        if (!BN) return;
        int i = (blockIdx.x - nAgg) * 256 + tid;
        if (i >= n * 32) return;
        int c0 = (i & 31) * 4;
        float4 sc = *(const float4*)&s_sc[c0];
        float4 sh = *(const float4*)&s_sh[c0];
        float4 v = ((const float4*)g_h)[i];
        float4 r;
        r.x = fmaxf(fmaf(v.x, sc.x, sh.x), 0.f);
        r.y = fmaxf(fmaf(v.y, sc.y, sh.y), 0.f);
        r.z = fmaxf(fmaf(v.z, sc.z, sh.z), 0.f);
        r.w = fmaxf(fmaf(v.w, sc.w, sh.w), 0.f);
        uint32_t h01, l01, h23, l23;
        split2(r.x, r.y, h01, l01);
        split2(r.z, r.w, h23, l23);
        ((uint2*)g_yH)[i] = make_uint2(h01, h23);
        ((uint2*)g_yL)[i] = make_uint2(l01, l23);
        return;
    }

    int node = blockIdx.x * 8 + (tid >> 5);
    int lane = tid & 31;
    if (node >= n) return;

    float4 sc = make_float4(1.f, 1.f, 1.f, 1.f), sh = make_float4(0.f, 0.f, 0.f, 0.f);
    if (BN) {
        sc = *(const float4*)&s_sc[lane * 4];
        sh = *(const float4*)&s_sh[lane * 4];
    }

    int beg = g_rowoff[node], end = g_rowoff[node + 1];
    const uint2* X2 = (const uint2*)X16;      // row = 32 uint2 (128 halfs)
    float4 acc = make_float4(0.f, 0.f, 0.f, 0.f);

    auto accum = [&](int2 ed) {
        float w = __int_as_float(ed.y);
        uint2 p = X2[(long)ed.x * 32 + lane];
        float2 f01 = __half22float2(*reinterpret_cast<__half2*>(&p.x));
        float2 f23 = __half22float2(*reinterpret_cast<__half2*>(&p.y));
        float4 v = make_float4(f01.x, f01.y, f23.x, f23.y);
        if (BN) {
            v.x = fmaxf(fmaf(v.x, sc.x, sh.x), 0.f);
            v.y = fmaxf(fmaf(v.y, sc.y, sh.y), 0.f);
            v.z = fmaxf(fmaf(v.z, sc.z, sh.z), 0.f);
            v.w = fmaxf(fmaf(v.w, sc.w, sh.w), 0.f);
        }
        acc.x += w * v.x; acc.y += w * v.y; acc.z += w * v.z; acc.w += w * v.w;
    };

    int e = beg;
    for (; e + 3 < end; e += 4) {
        int2 e0 = g_edge[e], e1 = g_edge[e + 1], e2 = g_edge[e + 2], e3 = g_edge[e + 3];
        accum(e0); accum(e1); accum(e2); accum(e3);
    }
    for (; e < end; e++) accum(g_edge[e]);

    float inv = 1.0f / fmaxf((float)(end - beg), 1.0f);
    acc.x *= inv; acc.y *= inv; acc.z *= inv; acc.w *= inv;
    uint32_t h01, l01, h23, l23;
    split2(acc.x, acc.y, h01, l01);
    split2(acc.z, acc.w, h23, l23);
    ((uint2*)g_mH)[(long)node * 32 + lane] = make_uint2(h01, h23);
    ((uint2*)g_mL)[(long)node * 32 + lane] = make_uint2(l01, l23);
}

// ---------------- standalone bnapply: h -> yH/yL (smem-cached coeffs) -----------
__global__ void __launch_bounds__(256)
bnapply_kernel(const float* __restrict__ stats,
               const float* __restrict__ gamma,
               const float* __restrict__ beta,
               float invM, int n4) {
    __shared__ float s_sc[128], s_sh[128];
    int tid = threadIdx.x;
    if (tid < 128) {
        float a, b;
        bn_coef(stats, gamma, beta, invM, tid, a, b);
        s_sc[tid] = a;
        s_sh[tid] = b;
    }
    __syncthreads();
    int i = blockIdx.x * 256 + tid;
    if (i >= n4) return;
    int c0 = (i & 31) * 4;
    float4 sc = *(const float4*)&s_sc[c0];
    float4 sh = *(const float4*)&s_sh[c0];
    float4 v = ((const float4*)g_h)[i];
    float4 r;
    r.x = fmaxf(fmaf(v.x, sc.x, sh.x), 0.f);
    r.y = fmaxf(fmaf(v.y, sc.y, sh.y), 0.f);
    r.z = fmaxf(fmaf(v.z, sc.z, sh.z), 0.f);
    r.w = fmaxf(fmaf(v.w, sc.w, sh.w), 0.f);
    uint32_t h01, l01, h23, l23;
    split2(r.x, r.y, h01, l01);
    split2(r.z, r.w, h23, l23);
    ((uint2*)g_yH)[i] = make_uint2(h01, h23);
    ((uint2*)g_yL)[i] = make_uint2(l01, l23);
}

// ---------------- final aggregate: out = mean(P16[src]) + R[node] + b2 ----------
__global__ void __launch_bounds__(256)
agg_final(const float* __restrict__ PR, const __half* __restrict__ PR16,
          const float* __restrict__ b2, float* __restrict__ out, int n) {
    int node = blockIdx.x * 8 + (threadIdx.x >> 5);
    int lane = threadIdx.x & 31;
    if (node >= n) return;
    int beg = g_rowoff[node], end = g_rowoff[node + 1];
    const uint32_t* P16 = (const uint32_t*)PR16;   // row = 64 uint32; P = first 32
    float2 acc = make_float2(0.f, 0.f);

    auto accum = [&](int2 ed) {
        float w = __int_as_float(ed.y);
        uint32_t p = P16[(long)ed.x * 64 + lane];
        float2 v = __half22float2(*reinterpret_cast<__half2*>(&p));
        acc.x += w * v.x; acc.y += w * v.y;
    };
    int e = beg;
    for (; e + 3 < end; e += 4) {
        int2 e0 = g_edge[e], e1 = g_edge[e + 1], e2 = g_edge[e + 2], e3 = g_edge[e + 3];
        accum(e0); accum(e1); accum(e2); accum(e3);
    }
    for (; e < end; e++) accum(g_edge[e]);

    float inv = 1.0f / fmaxf((float)(end - beg), 1.0f);
    float2 r  = ((const float2*)PR)[(long)node * 64 + 32 + lane];   // R fp32
    float2 bb = ((const float2*)b2)[lane];
    float2 o;
    o.x = acc.x * inv + r.x + bb.x;
    o.y = acc.y * inv + r.y + bb.y;
    ((float2*)out)[(long)node * 32 + lane] = o;
}

// ---------------- mma.sync GEMM (128x128), smem-staged stats, fp16 copy out -----
// HALVES=2: A = [m|r], K=256. HALVES=1: A = r only, K=128.
template <int TN, int HALVES, bool STATS>
__global__ void __launch_bounds__(256)
gemm2(const __nv_bfloat16* __restrict__ mH, const __nv_bfloat16* __restrict__ mL,
      const __nv_bfloat16* __restrict__ rH, const __nv_bfloat16* __restrict__ rL,
      const __nv_bfloat16* __restrict__ BH, const __nv_bfloat16* __restrict__ BL,
      const float* __restrict__ bias, float* __restrict__ C, __half* __restrict__ C16,
      float* __restrict__ stats, int M) {
    constexpr int NWC = TN / 2;
    constexpr int NF  = NWC / 8;
    constexpr int CH  = HALVES * 4;
    constexpr int offAhi = 0;
    constexpr int offAlo = 128 * 80;
    constexpr int offBhi = 2 * 128 * 80;
    constexpr int offBlo = 2 * 128 * 80 + TN * 80;
    constexpr int STAGE  = 2 * 128 * 80 + 2 * TN * 80;

    extern __shared__ __align__(16) char smem[];
    const uint32_t sbase = smem_u32(smem);

    const int tid = threadIdx.x;
    const int lane = tid & 31, wid = tid >> 5;
    const int wm = wid & 3, wn = wid >> 2;
    const int row0 = blockIdx.x * 128;

    float acc[2][NF][4];
    #pragma unroll
    for (int mb = 0; mb < 2; mb++)
        #pragma unroll
        for (int f = 0; f < NF; f++)
            #pragma unroll
            for (int q = 0; q < 4; q++) acc[mb][f][q] = 0.f;

    auto load_chunk = [&](int ch, int buf) {
        const int half = ch >> 2, q = ch & 3;
        const __nv_bfloat16* Ah = (HALVES == 2 && half == 0) ? mH : rH;
        const __nv_bfloat16* Al = (HALVES == 2 && half == 0) ? mL : rL;
        const int acol = q * 32;
        const int bcol = half * 128 + q * 32;
        const uint32_t base = sbase + buf * STAGE;
        #pragma unroll
        for (int t = 0; t < 2; t++) {
            int idx = tid + t * 256;
            int r = idx >> 2, c = idx & 3;
            int gr = row0 + r;
            const long aoff = (long)gr * 128 + acol + c * 8;
            cpa16(base + offAhi + r * 80 + c * 16, Ah + aoff, gr < M);
            cpa16(base + offAlo + r * 80 + c * 16, Al + aoff, gr < M);
        }
        #pragma unroll
        for (int t = 0; t < TN / 64; t++) {
            int idx = tid + t * 256;
            int n = idx >> 2, c = idx & 3;
            const long boff = (long)n * 256 + bcol + c * 8;
            cpa16(base + offBhi + n * 80 + c * 16, BH + boff, true);
            cpa16(base + offBlo + n * 80 + c * 16, BL + boff, true);
        }
        asm volatile("cp.async.commit_group;" ::: "memory");
    };

    load_chunk(0, 0);

    for (int ch = 0; ch < CH; ch++) {
        const int buf = ch & 1;
        if (ch + 1 < CH) {
            load_chunk(ch + 1, buf ^ 1);
            asm volatile("cp.async.wait_group 1;" ::: "memory");
        } else {
            asm volatile("cp.async.wait_group 0;" ::: "memory");
        }
        __syncthreads();
        const uint32_t base = sbase + buf * STAGE;

        #pragma unroll
        for (int ks = 0; ks < 2; ks++) {
            uint32_t aH2[2][4], aL2[2][4];
            #pragma unroll
            for (int mb = 0; mb < 2; mb++) {
                uint32_t rterm = (wm * 32 + mb * 16 + (lane & 15)) * 80
                               + ks * 32 + ((lane >> 4) << 4);
                ldsm_x4(base + offAhi + rterm, aH2[mb]);
                ldsm_x4(base + offAlo + rterm, aL2[mb]);
            }
            #pragma unroll
            for (int f = 0; f < NF / 2; f++) {
                int n = wn * NWC + f * 16 + (lane & 7) + ((lane >> 3) & 1) * 8;
                uint32_t boff = n * 80 + ks * 32 + ((lane >> 4) << 4);
                uint32_t bH[4], bL[4];
                ldsm_x4(base + offBhi + boff, bH);
                ldsm_x4(base + offBlo + boff, bL);
                #pragma unroll
                for (int mb = 0; mb < 2; mb++) {
                    mma16816(acc[mb][2 * f],     aH2[mb], bH[0], bH[2]);
                    mma16816(acc[mb][2 * f + 1], aH2[mb], bH[1], bH[3]);
                    mma16816(acc[mb][2 * f],     aL2[mb], bH[0], bH[2]);
                    mma16816(acc[mb][2 * f + 1], aL2[mb], bH[1], bH[3]);
                    mma16816(acc[mb][2 * f],     aH2[mb], bL[0], bL[2]);
                    mma16816(acc[mb][2 * f + 1], aH2[mb], bL[1], bL[3]);
                }
            }
        }
        __syncthreads();
    }

    // epilogue: stats staged in smem (pipeline smem is dead past last sync)
    float* s_red = (float*)smem;               // 256 floats
    if (STATS) {
        if (tid < 256) s_red[tid] = 0.f;
        __syncthreads();
    }

    const int rA = row0 + wm * 32 + (lane >> 2);
    const int cbase = wn * NWC + (lane & 3) * 2;
    #pragma unroll
    for (int nf = 0; nf < NF; nf++) {
        int col = cbase + nf * 8;
        float bx = bias ? bias[col] : 0.f;
        float by = bias ? bias[col + 1] : 0.f;
        float s0 = 0.f, q0 = 0.f, s1 = 0.f, q1 = 0.f;
        #pragma unroll
        for (int mb = 0; mb < 2; mb++) {
            int r0r = rA + mb * 16;
            if (r0r < M) {
                float vx = acc[mb][nf][0] + bx, vy = acc[mb][nf][1] + by;
                *(float2*)(C + (long)r0r * TN + col) = make_float2(vx, vy);
                ((__half2*)C16)[(long)r0r * 64 + (col >> 1)] = __floats2half2_rn(vx, vy);
                if (STATS) { s0 += vx; q0 += vx * vx; s1 += vy; q1 += vy * vy; }
            }
            int r1r = r0r + 8;
            if (r1r < M) {
                float vx = acc[mb][nf][2] + bx, vy = acc[mb][nf][3] + by;
                *(float2*)(C + (long)r1r * TN + col) = make_float2(vx, vy);
                ((__half2*)C16)[(long)r1r * 64 + (col >> 1)] = __floats2half2_rn(vx, vy);
                if (STATS) { s0 += vx; q0 += vx * vx; s1 += vy; q1 += vy * vy; }
            }
        }
        if (STATS) {
            #pragma unroll
            for (int o = 4; o < 32; o <<= 1) {
                s0 += __shfl_xor_sync(0xFFFFFFFFu, s0, o);
                q0 += __shfl_xor_sync(0xFFFFFFFFu, q0, o);
                s1 += __shfl_xor_sync(0xFFFFFFFFu, s1, o);
                q1 += __shfl_xor_sync(0xFFFFFFFFu, q1, o);
            }
            if ((lane >> 2) == 0) {
                atomicAdd(&s_red[col], s0);
                atomicAdd(&s_red[128 + col], q0);
                atomicAdd(&s_red[col + 1], s1);
                atomicAdd(&s_red[128 + col + 1], q1);
            }
        }
    }
    if (STATS) {
        __syncthreads();
        if (tid < 256) atomicAdd(&stats[tid], s_red[tid]);
    }
}

// ---------------- launch --------------------------------------------------------
extern "C" void kernel_launch(void* const* d_in, const int* in_sizes, int n_in,
                              void* d_out, int out_size) {
    const float* x   = (const float*)d_in[0];
    const int*   ei  = (const int*)d_in[1];
    const float* ew  = (const float*)d_in[2];
    const float* Wl0 = (const float*)d_in[3];
    const float* Wr0 = (const float*)d_in[4];
    const float* b0  = (const float*)d_in[5];
    const float* Wl1 = (const float*)d_in[6];
    const float* Wr1 = (const float*)d_in[7];
    const float* b1  = (const float*)d_in[8];
    const float* Wl2 = (const float*)d_in[9];
    const float* Wr2 = (const float*)d_in[10];
    const float* b2  = (const float*)d_in[11];
    const float* g0  = (const float*)d_in[12];
    const float* be0 = (const float*)d_in[13];
    const float* g1  = (const float*)d_in[14];
    const float* be1 = (const float*)d_in[15];
    float* out = (float*)d_out;

    int N = in_sizes[0] / 128;
    int E = in_sizes[2];

    float *h, *stats0, *stats1;
    __half *x16, *h16;
    __nv_bfloat16 *xH, *xL, *mH, *mL, *yH, *yL, *BH, *BL;
    cudaGetSymbolAddress((void**)&h,   g_h);
    cudaGetSymbolAddress((void**)&x16, g_x16);
    cudaGetSymbolAddress((void**)&h16, g_h16);
    cudaGetSymbolAddress((void**)&xH, g_xH);
    cudaGetSymbolAddress((void**)&xL, g_xL);
    cudaGetSymbolAddress((void**)&mH, g_mH);
    cudaGetSymbolAddress((void**)&mL, g_mL);
    cudaGetSymbolAddress((void**)&yH, g_yH);
    cudaGetSymbolAddress((void**)&yL, g_yL);
    cudaGetSymbolAddress((void**)&BH, g_BH);
    cudaGetSymbolAddress((void**)&BL, g_BL);
    cudaGetSymbolAddress((void**)&stats0, g_statsA);
    stats1 = stats0 + 256;

    constexpr int SM128 = 2 * (2 * 128 * 80 + 2 * 128 * 80);  // 81920
    cudaFuncSetAttribute(gemm2<128, 2, true>,  cudaFuncAttributeMaxDynamicSharedMemorySize, SM128);
    cudaFuncSetAttribute(gemm2<128, 1, false>, cudaFuncAttributeMaxDynamicSharedMemorySize, SM128);

    const int T = 256;
    int gE = (E + T - 1) / T;
    int gW = (N + 7) / 8;
    int gGemm = (N + 127) / 128;
    int gApply = (N * 32 + T - 1) / T;
    int gScan = (N + 1023) / 1024;
    float invM = 1.0f / (float)N;

    prep_kernel<<<gApply, T>>>(x, ei + E, Wl0, Wr0, Wl1, Wr1, Wl2, Wr2, N * 32, E);
    scan_kernel<<<gScan, 1024>>>(N);
    scatter_kernel<<<gE, T>>>(ei, ei + E, ew, E);

    // ----- layer 0 -----
    layer_mid<false><<<gW, T>>>(x16, nullptr, nullptr, nullptr, invM, N, gW);
    gemm2<128, 2, true><<<gGemm, T, SM128>>>(mH, mL, xH, xL, BH, BL, b0, h, h16, stats0, N);

    // ----- layer 1 (fused bnapply + aggregate-with-BN, fp16 gather) -----
    layer_mid<true><<<gW + gApply, T>>>(h16, stats0, g0, be0, invM, N, gW);
    gemm2<128, 2, true><<<gGemm, T, SM128>>>(mH, mL, yH, yL, BH + 32768, BL + 32768, b1, h, h16, stats1, N);

    // ----- layer 2 (bnapply -> GEMM -> final aggregate, fp16 P gather) -----
    bnapply_kernel<<<gApply, T>>>(stats1, g1, be1, invM, N * 32);
    gemm2<128, 1, false><<<gGemm, T, SM128>>>(nullptr, nullptr, yH, yL,
                                              BH + 65536, BL + 65536, nullptr, h, h16, nullptr, N);
    agg_final<<<gW, T>>>(h, h16, b2, out, N);
}

// round 16
// speedup vs baseline: 1.0387x; 1.0387x over previous
#include <cuda_runtime.h>
#include <cuda_bf16.h>
#include <cuda_fp16.h>
#include <cstdint>

#define NNODES 50000
#define NEDGES 600000

// ---------------- scratch (device globals) -------------------------------------
__device__ int   g_deg[NNODES];          // zero-init; re-zeroed by scan
__device__ int   g_rowoff[NNODES + 1];
__device__ int   g_woff[NNODES];
__device__ int   g_blkagg[64];
__device__ int   g_blkinc[64];
__device__ int   g_flag[64];             // lookback flags; reset by scatter
__device__ int2  g_edge[NEDGES];         // (src, w_bits)
__device__ float g_h[NNODES * 128];      // fp32 only for layer2 [P|R]
__device__ __half g_x16[NNODES * 128];   // fp16 gather copy of x
__device__ __half g_h16[NNODES * 128];   // fp16 h (layers 0/1 sole copy; layer2 P)
__device__ __nv_bfloat16 g_xH[NNODES * 128], g_xL[NNODES * 128];
__device__ __nv_bfloat16 g_mH[NNODES * 128], g_mL[NNODES * 128];
__device__ __nv_bfloat16 g_yH[NNODES * 128], g_yL[NNODES * 128];
__device__ __nv_bfloat16 g_BH[98304], g_BL[98304];   // W0 W1 W2, [n][k] stride 256
__device__ float g_statsA[512];          // layer0: [0,256) ; layer1: [256,512)

// ---------------- helpers ------------------------------------------------------
__device__ __forceinline__ uint32_t smem_u32(const void* p) {
    uint32_t a;
    asm("{ .reg .u64 t; cvta.to.shared.u64 t, %1; cvt.u32.u64 %0, t; }" : "=r"(a) : "l"(p));
    return a;
}
__device__ __forceinline__ void ldsm_x4(uint32_t addr, uint32_t r[4]) {
    asm volatile("ldmatrix.sync.aligned.m8n8.x4.shared.b16 {%0,%1,%2,%3}, [%4];"
        : "=r"(r[0]), "=r"(r[1]), "=r"(r[2]), "=r"(r[3]) : "r"(addr));
}
__device__ __forceinline__ void mma16816(float c[4], const uint32_t a[4], uint32_t b0, uint32_t b1) {
    asm volatile("mma.sync.aligned.m16n8k16.row.col.f32.bf16.bf16.f32 "
        "{%0,%1,%2,%3}, {%4,%5,%6,%7}, {%8,%9}, {%0,%1,%2,%3};"
        : "+f"(c[0]), "+f"(c[1]), "+f"(c[2]), "+f"(c[3])
        : "r"(a[0]), "r"(a[1]), "r"(a[2]), "r"(a[3]), "r"(b0), "r"(b1));
}
__device__ __forceinline__ void cpa16(uint32_t dst, const void* src, bool pred) {
    int sz = pred ? 16 : 0;
    asm volatile("cp.async.cg.shared.global [%0], [%1], 16, %2;"
        :: "r"(dst), "l"(src), "r"(sz) : "memory");
}
__device__ __forceinline__ void split2(float a, float b, uint32_t& hi, uint32_t& lo) {
    __nv_bfloat162 h = __floats2bfloat162_rn(a, b);
    float ha = __bfloat162float(h.x), hb = __bfloat162float(h.y);
    __nv_bfloat162 l = __floats2bfloat162_rn(a - ha, b - hb);
    hi = *reinterpret_cast<uint32_t*>(&h);
    lo = *reinterpret_cast<uint32_t*>(&l);
}
__device__ __forceinline__ float4 h16_load4(const __half* p, long idx4) {
    uint2 u = ((const uint2*)p)[idx4];
    float2 f01 = __half22float2(*reinterpret_cast<__half2*>(&u.x));
    float2 f23 = __half22float2(*reinterpret_cast<__half2*>(&u.y));
    return make_float4(f01.x, f01.y, f23.x, f23.y);
}
// BN coefficients from single-address raw stats
__device__ __forceinline__ void bn_coef(const float* __restrict__ stats,
                                        const float* __restrict__ gamma,
                                        const float* __restrict__ beta,
                                        float invM, int c, float& sc, float& sh) {
    float mu  = stats[c] * invM;
    float var = stats[128 + c] * invM - mu * mu;
    float g = gamma[c] * rsqrtf(var + 1e-5f);
    sc = g;
    sh = beta[c] - mu * g;
}

// ---------------- prep: x split + x16 + weights + degree count + stats zero ----
__global__ void prep_kernel(const float* __restrict__ x,
                            const int* __restrict__ dst,
                            const float* __restrict__ Wl0, const float* __restrict__ Wr0,
                            const float* __restrict__ Wl1, const float* __restrict__ Wr1,
                            const float* __restrict__ Wl2, const float* __restrict__ Wr2,
                            int n4, int E) {
    int gid = blockIdx.x * blockDim.x + threadIdx.x;
    if (gid < n4) {
        float4 v = ((const float4*)x)[gid];
        uint32_t h01, l01, h23, l23;
        split2(v.x, v.y, h01, l01);
        split2(v.z, v.w, h23, l23);
        ((uint2*)g_xH)[gid] = make_uint2(h01, h23);
        ((uint2*)g_xL)[gid] = make_uint2(l01, l23);
        __half2 p01 = __floats2half2_rn(v.x, v.y);
        __half2 p23 = __floats2half2_rn(v.z, v.w);
        uint2 u;
        u.x = *reinterpret_cast<uint32_t*>(&p01);
        u.y = *reinterpret_cast<uint32_t*>(&p23);
        ((uint2*)g_x16)[gid] = u;
    }
    if (gid < E) atomicAdd(&g_deg[dst[gid]], 1);
    if (gid < 512) g_statsA[gid] = 0.f;
    if (gid < 98304) {
        float v;
        int t;
        if (gid < 32768) {
            t = gid;
            int n = t >> 8, k = t & 255;
            v = (k < 128) ? Wl0[k * 128 + n] : Wr0[(k - 128) * 128 + n];
        } else if (gid < 65536) {
            t = gid - 32768;
            int n = t >> 8, k = t & 255;
            v = (k < 128) ? Wl1[k * 128 + n] : Wr1[(k - 128) * 128 + n];
        } else {
            t = gid - 65536;
            int n = t >> 8, k = t & 255;
            if (k < 128) v = (n < 64) ? Wl2[k * 64 + n] : Wr2[k * 64 + (n - 64)];
            else v = 0.f;
        }
        __nv_bfloat16 h = __float2bfloat16_rn(v);
        g_BH[gid] = h;
        g_BL[gid] = __float2bfloat16_rn(v - __bfloat162float(h));
    }
}

// ---------------- single-kernel decoupled-lookback scan -------------------------
__global__ void scan_kernel(int n) {
    const int b = blockIdx.x, tid = threadIdx.x;
    const int lane = tid & 31, wid = tid >> 5;
    int i = b * 1024 + tid;
    int v = (i < n) ? g_deg[i] : 0;
    int x = v;
    #pragma unroll
    for (int o = 1; o < 32; o <<= 1) {
        int t2 = __shfl_up_sync(0xFFFFFFFFu, x, o);
        if (lane >= o) x += t2;
    }
    __shared__ int ws[32];
    __shared__ int sh_base, sh_tot;
    if (lane == 31) ws[wid] = x;
    __syncthreads();
    if (wid == 0) {
        int y = ws[lane];
        #pragma unroll
        for (int o = 1; o < 32; o <<= 1) {
            int t2 = __shfl_up_sync(0xFFFFFFFFu, y, o);
            if (lane >= o) y += t2;
        }
        ws[lane] = y;
    }
    __syncthreads();
    const int S = ws[31];
    if (tid == 0) {
        g_blkagg[b] = S;
        __threadfence();
        atomicExch(&g_flag[b], 1);
        int excl = 0;
        for (int p = b - 1; p >= 0; ) {
            int f;
            do { f = atomicAdd(&g_flag[p], 0); } while (f == 0);
            __threadfence();
            if (f == 2) { excl += g_blkinc[p]; break; }
            excl += g_blkagg[p];
            p--;
        }
        g_blkinc[b] = excl + S;
        __threadfence();
        atomicExch(&g_flag[b], 2);
        sh_base = excl;
        sh_tot  = excl + S;
    }
    __syncthreads();
    int excl_i = x - v + (wid ? ws[wid - 1] : 0) + sh_base;
    if (i < n) {
        g_rowoff[i] = excl_i;
        g_woff[i]   = excl_i;
        g_deg[i]    = 0;
    }
    if (b == gridDim.x - 1 && tid == 0) g_rowoff[n] = sh_tot;
}

__global__ void scatter_kernel(const int* __restrict__ src, const int* __restrict__ dst,
                               const float* __restrict__ w, int e) {
    int i = blockIdx.x * blockDim.x + threadIdx.x;
    if (i < 64) g_flag[i] = 0;              // reset lookback flags for next replay
    if (i < e) {
        int d = dst[i];
        int p = atomicAdd(&g_woff[d], 1);
        g_edge[p] = make_int2(src[i], __float_as_int(w[i]));
    }
}

// ---------------- fused aggregate (+BN gather, fp16 source) & bnapply -----------
template <bool BN>
__global__ void __launch_bounds__(256)
layer_mid(const __half* __restrict__ X16,
          const float* __restrict__ stats,
          const float* __restrict__ gamma,
          const float* __restrict__ beta,
          float invM, int n, int nAgg) {
    __shared__ float s_sc[128], s_sh[128];
    int tid = threadIdx.x;
    if (BN) {
        if (tid < 128) {
            float a, b;
            bn_coef(stats, gamma, beta, invM, tid, a, b);
            s_sc[tid] = a;
            s_sh[tid] = b;
        }
        __syncthreads();
    }

    if ((int)blockIdx.x >= nAgg) {
        if (!BN) return;
        int i = (blockIdx.x - nAgg) * 256 + tid;
        if (i >= n * 32) return;
        int c0 = (i & 31) * 4;
        float4 sc = *(const float4*)&s_sc[c0];
        float4 sh = *(const float4*)&s_sh[c0];
        float4 v = h16_load4(g_h16, i);
        float4 r;
        r.x = fmaxf(fmaf(v.x, sc.x, sh.x), 0.f);
        r.y = fmaxf(fmaf(v.y, sc.y, sh.y), 0.f);
        r.z = fmaxf(fmaf(v.z, sc.z, sh.z), 0.f);
        r.w = fmaxf(fmaf(v.w, sc.w, sh.w), 0.f);
        uint32_t h01, l01, h23, l23;
        split2(r.x, r.y, h01, l01);
        split2(r.z, r.w, h23, l23);
        ((uint2*)g_yH)[i] = make_uint2(h01, h23);
        ((uint2*)g_yL)[i] = make_uint2(l01, l23);
        return;
    }

    int node = blockIdx.x * 8 + (tid >> 5);
    int lane = tid & 31;
    if (node >= n) return;

    float4 sc = make_float4(1.f, 1.f, 1.f, 1.f), sh = make_float4(0.f, 0.f, 0.f, 0.f);
    if (BN) {
        sc = *(const float4*)&s_sc[lane * 4];
        sh = *(const float4*)&s_sh[lane * 4];
    }

    int beg = g_rowoff[node], end = g_rowoff[node + 1];
    float4 acc = make_float4(0.f, 0.f, 0.f, 0.f);

    auto accum = [&](int2 ed) {
        float w = __int_as_float(ed.y);
        float4 v = h16_load4(X16, (long)ed.x * 32 + lane);
        if (BN) {
            v.x = fmaxf(fmaf(v.x, sc.x, sh.x), 0.f);
            v.y = fmaxf(fmaf(v.y, sc.y, sh.y), 0.f);
            v.z = fmaxf(fmaf(v.z, sc.z, sh.z), 0.f);
            v.w = fmaxf(fmaf(v.w, sc.w, sh.w), 0.f);
        }
        acc.x += w * v.x; acc.y += w * v.y; acc.z += w * v.z; acc.w += w * v.w;
    };

    int e = beg;
    for (; e + 3 < end; e += 4) {
        int2 e0 = g_edge[e], e1 = g_edge[e + 1], e2 = g_edge[e + 2], e3 = g_edge[e + 3];
        accum(e0); accum(e1); accum(e2); accum(e3);
    }
    for (; e < end; e++) accum(g_edge[e]);

    float inv = 1.0f / fmaxf((float)(end - beg), 1.0f);
    acc.x *= inv; acc.y *= inv; acc.z *= inv; acc.w *= inv;
    uint32_t h01, l01, h23, l23;
    split2(acc.x, acc.y, h01, l01);
    split2(acc.z, acc.w, h23, l23);
    ((uint2*)g_mH)[(long)node * 32 + lane] = make_uint2(h01, h23);
    ((uint2*)g_mL)[(long)node * 32 + lane] = make_uint2(l01, l23);
}

// ---------------- standalone bnapply: h16 -> yH/yL ------------------------------
__global__ void __launch_bounds__(256)
bnapply_kernel(const float* __restrict__ stats,
               const float* __restrict__ gamma,
               const float* __restrict__ beta,
               float invM, int n4) {
    __shared__ float s_sc[128], s_sh[128];
    int tid = threadIdx.x;
    if (tid < 128) {
        float a, b;
        bn_coef(stats, gamma, beta, invM, tid, a, b);
        s_sc[tid] = a;
        s_sh[tid] = b;
    }
    __syncthreads();
    int i = blockIdx.x * 256 + tid;
    if (i >= n4) return;
    int c0 = (i & 31) * 4;
    float4 sc = *(const float4*)&s_sc[c0];
    float4 sh = *(const float4*)&s_sh[c0];
    float4 v = h16_load4(g_h16, i);
    float4 r;
    r.x = fmaxf(fmaf(v.x, sc.x, sh.x), 0.f);
    r.y = fmaxf(fmaf(v.y, sc.y, sh.y), 0.f);
    r.z = fmaxf(fmaf(v.z, sc.z, sh.z), 0.f);
    r.w = fmaxf(fmaf(v.w, sc.w, sh.w), 0.f);
    uint32_t h01, l01, h23, l23;
    split2(r.x, r.y, h01, l01);
    split2(r.z, r.w, h23, l23);
    ((uint2*)g_yH)[i] = make_uint2(h01, h23);
    ((uint2*)g_yL)[i] = make_uint2(l01, l23);
}

// ---------------- final aggregate: out = mean(P16[src]) + R[node] + b2 ----------
__global__ void __launch_bounds__(256)
agg_final(const float* __restrict__ PR, const __half* __restrict__ PR16,
          const float* __restrict__ b2, float* __restrict__ out, int n) {
    int node = blockIdx.x * 8 + (threadIdx.x >> 5);
    int lane = threadIdx.x & 31;
    if (node >= n) return;
    int beg = g_rowoff[node], end = g_rowoff[node + 1];
    const uint32_t* P16 = (const uint32_t*)PR16;   // row = 64 uint32; P = first 32
    float2 acc = make_float2(0.f, 0.f);

    auto accum = [&](int2 ed) {
        float w = __int_as_float(ed.y);
        uint32_t p = P16[(long)ed.x * 64 + lane];
        float2 v = __half22float2(*reinterpret_cast<__half2*>(&p));
        acc.x += w * v.x; acc.y += w * v.y;
    };
    int e = beg;
    for (; e + 3 < end; e += 4) {
        int2 e0 = g_edge[e], e1 = g_edge[e + 1], e2 = g_edge[e + 2], e3 = g_edge[e + 3];
        accum(e0); accum(e1); accum(e2); accum(e3);
    }
    for (; e < end; e++) accum(g_edge[e]);

    float inv = 1.0f / fmaxf((float)(end - beg), 1.0f);
    float2 r  = ((const float2*)PR)[(long)node * 64 + 32 + lane];   // R fp32
    float2 bb = ((const float2*)b2)[lane];
    float2 o;
    o.x = acc.x * inv + r.x + bb.x;
    o.y = acc.y * inv + r.y + bb.y;
    ((float2*)out)[(long)node * 32 + lane] = o;
}

// ---------------- mma.sync GEMM (128x128): fp16-primary output ------------------
// HALVES=2: A = [m|r], K=256. HALVES=1: A = r only, K=128.
// WF32: also write fp32 C (layer 2 only).
template <int TN, int HALVES, bool STATS, bool WF32>
__global__ void __launch_bounds__(256)
gemm2(const __nv_bfloat16* __restrict__ mH, const __nv_bfloat16* __restrict__ mL,
      const __nv_bfloat16* __restrict__ rH, const __nv_bfloat16* __restrict__ rL,
      const __nv_bfloat16* __restrict__ BH, const __nv_bfloat16* __restrict__ BL,
      const float* __restrict__ bias, float* __restrict__ C, __half* __restrict__ C16,
      float* __restrict__ stats, int M) {
    constexpr int NWC = TN / 2;
    constexpr int NF  = NWC / 8;
    constexpr int CH  = HALVES * 4;
    constexpr int offAhi = 0;
    constexpr int offAlo = 128 * 80;
    constexpr int offBhi = 2 * 128 * 80;
    constexpr int offBlo = 2 * 128 * 80 + TN * 80;
    constexpr int STAGE  = 2 * 128 * 80 + 2 * TN * 80;

    extern __shared__ __align__(16) char smem[];
    const uint32_t sbase = smem_u32(smem);

    const int tid = threadIdx.x;
    const int lane = tid & 31, wid = tid >> 5;
    const int wm = wid & 3, wn = wid >> 2;
    const int row0 = blockIdx.x * 128;

    float acc[2][NF][4];
    #pragma unroll
    for (int mb = 0; mb < 2; mb++)
        #pragma unroll
        for (int f = 0; f < NF; f++)
            #pragma unroll
            for (int q = 0; q < 4; q++) acc[mb][f][q] = 0.f;

    auto load_chunk = [&](int ch, int buf) {
        const int half = ch >> 2, q = ch & 3;
        const __nv_bfloat16* Ah = (HALVES == 2 && half == 0) ? mH : rH;
        const __nv_bfloat16* Al = (HALVES == 2 && half == 0) ? mL : rL;
        const int acol = q * 32;
        const int bcol = half * 128 + q * 32;
        const uint32_t base = sbase + buf * STAGE;
        #pragma unroll
        for (int t = 0; t < 2; t++) {
            int idx = tid + t * 256;
            int r = idx >> 2, c = idx & 3;
            int gr = row0 + r;
            const long aoff = (long)gr * 128 + acol + c * 8;
            cpa16(base + offAhi + r * 80 + c * 16, Ah + aoff, gr < M);
            cpa16(base + offAlo + r * 80 + c * 16, Al + aoff, gr < M);
        }
        #pragma unroll
        for (int t = 0; t < TN / 64; t++) {
            int idx = tid + t * 256;
            int n = idx >> 2, c = idx & 3;
            const long boff = (long)n * 256 + bcol + c * 8;
            cpa16(base + offBhi + n * 80 + c * 16, BH + boff, true);
            cpa16(base + offBlo + n * 80 + c * 16, BL + boff, true);
        }
        asm volatile("cp.async.commit_group;" ::: "memory");
    };

    load_chunk(0, 0);

    for (int ch = 0; ch < CH; ch++) {
        const int buf = ch & 1;
        if (ch + 1 < CH) {
            load_chunk(ch + 1, buf ^ 1);
            asm volatile("cp.async.wait_group 1;" ::: "memory");
        } else {
            asm volatile("cp.async.wait_group 0;" ::: "memory");
        }
        __syncthreads();
        const uint32_t base = sbase + buf * STAGE;

        #pragma unroll
        for (int ks = 0; ks < 2; ks++) {
            uint32_t aH2[2][4], aL2[2][4];
            #pragma unroll
            for (int mb = 0; mb < 2; mb++) {
                uint32_t rterm = (wm * 32 + mb * 16 + (lane & 15)) * 80
                               + ks * 32 + ((lane >> 4) << 4);
                ldsm_x4(base + offAhi + rterm, aH2[mb]);
                ldsm_x4(base + offAlo + rterm, aL2[mb]);
            }
            #pragma unroll
            for (int f = 0; f < NF / 2; f++) {
                int n = wn * NWC + f * 16 + (lane & 7) + ((lane >> 3) & 1) * 8;
                uint32_t boff = n * 80 + ks * 32 + ((lane >> 4) << 4);
                uint32_t bH[4], bL[4];
                ldsm_x4(base + offBhi + boff, bH);
                ldsm_x4(base + offBlo + boff, bL);
                #pragma unroll
                for (int mb = 0; mb < 2; mb++) {
                    mma16816(acc[mb][2 * f],     aH2[mb], bH[0], bH[2]);
                    mma16816(acc[mb][2 * f + 1], aH2[mb], bH[1], bH[3]);
                    mma16816(acc[mb][2 * f],     aL2[mb], bH[0], bH[2]);
                    mma16816(acc[mb][2 * f + 1], aL2[mb], bH[1], bH[3]);
                    mma16816(acc[mb][2 * f],     aH2[mb], bL[0], bL[2]);
                    mma16816(acc[mb][2 * f + 1], aH2[mb], bL[1], bL[3]);
                }
            }
        }
        __syncthreads();
    }

    // epilogue: stats staged in smem (pipeline smem dead past last sync)
    float* s_red = (float*)smem;               // 256 floats
    if (STATS) {
        if (tid < 256) s_red[tid] = 0.f;
        __syncthreads();
    }

    const int rA = row0 + wm * 32 + (lane >> 2);
    const int cbase = wn * NWC + (lane & 3) * 2;
    #pragma unroll
    for (int nf = 0; nf < NF; nf++) {
        int col = cbase + nf * 8;
        float bx = bias ? bias[col] : 0.f;
        float by = bias ? bias[col + 1] : 0.f;
        float s0 = 0.f, q0 = 0.f, s1 = 0.f, q1 = 0.f;
        #pragma unroll
        for (int mb = 0; mb < 2; mb++) {
            int r0r = rA + mb * 16;
            if (r0r < M) {
                float vx = acc[mb][nf][0] + bx, vy = acc[mb][nf][1] + by;
                if (WF32) *(float2*)(C + (long)r0r * TN + col) = make_float2(vx, vy);
                ((__half2*)C16)[(long)r0r * 64 + (col >> 1)] = __floats2half2_rn(vx, vy);
                if (STATS) { s0 += vx; q0 += vx * vx; s1 += vy; q1 += vy * vy; }
            }
            int r1r = r0r + 8;
            if (r1r < M) {
                float vx = acc[mb][nf][2] + bx, vy = acc[mb][nf][3] + by;
                if (WF32) *(float2*)(C + (long)r1r * TN + col) = make_float2(vx, vy);
                ((__half2*)C16)[(long)r1r * 64 + (col >> 1)] = __floats2half2_rn(vx, vy);
                if (STATS) { s0 += vx; q0 += vx * vx; s1 += vy; q1 += vy * vy; }
            }
        }
        if (STATS) {
            #pragma unroll
            for (int o = 4; o < 32; o <<= 1) {
                s0 += __shfl_xor_sync(0xFFFFFFFFu, s0, o);
                q0 += __shfl_xor_sync(0xFFFFFFFFu, q0, o);
                s1 += __shfl_xor_sync(0xFFFFFFFFu, s1, o);
                q1 += __shfl_xor_sync(0xFFFFFFFFu, q1, o);
            }
            if ((lane >> 2) == 0) {
                atomicAdd(&s_red[col], s0);
                atomicAdd(&s_red[128 + col], q0);
                atomicAdd(&s_red[col + 1], s1);
                atomicAdd(&s_red[128 + col + 1], q1);
            }
        }
    }
    if (STATS) {
        __syncthreads();
        if (tid < 256) atomicAdd(&stats[tid], s_red[tid]);
    }
}

// ---------------- launch --------------------------------------------------------
extern "C" void kernel_launch(void* const* d_in, const int* in_sizes, int n_in,
                              void* d_out, int out_size) {
    const float* x   = (const float*)d_in[0];
    const int*   ei  = (const int*)d_in[1];
    const float* ew  = (const float*)d_in[2];
    const float* Wl0 = (const float*)d_in[3];
    const float* Wr0 = (const float*)d_in[4];
    const float* b0  = (const float*)d_in[5];
    const float* Wl1 = (const float*)d_in[6];
    const float* Wr1 = (const float*)d_in[7];
    const float* b1  = (const float*)d_in[8];
    const float* Wl2 = (const float*)d_in[9];
    const float* Wr2 = (const float*)d_in[10];
    const float* b2  = (const float*)d_in[11];
    const float* g0  = (const float*)d_in[12];
    const float* be0 = (const float*)d_in[13];
    const float* g1  = (const float*)d_in[14];
    const float* be1 = (const float*)d_in[15];
    float* out = (float*)d_out;

    int N = in_sizes[0] / 128;
    int E = in_sizes[2];

    float *h, *stats0, *stats1;
    __half *x16, *h16;
    __nv_bfloat16 *xH, *xL, *mH, *mL, *yH, *yL, *BH, *BL;
    cudaGetSymbolAddress((void**)&h,   g_h);
    cudaGetSymbolAddress((void**)&x16, g_x16);
    cudaGetSymbolAddress((void**)&h16, g_h16);
    cudaGetSymbolAddress((void**)&xH, g_xH);
    cudaGetSymbolAddress((void**)&xL, g_xL);
    cudaGetSymbolAddress((void**)&mH, g_mH);
    cudaGetSymbolAddress((void**)&mL, g_mL);
    cudaGetSymbolAddress((void**)&yH, g_yH);
    cudaGetSymbolAddress((void**)&yL, g_yL);
    cudaGetSymbolAddress((void**)&BH, g_BH);
    cudaGetSymbolAddress((void**)&BL, g_BL);
    cudaGetSymbolAddress((void**)&stats0, g_statsA);
    stats1 = stats0 + 256;

    constexpr int SM128 = 2 * (2 * 128 * 80 + 2 * 128 * 80);  // 81920
    cudaFuncSetAttribute((const void*)gemm2<128, 2, true, false>,
                         cudaFuncAttributeMaxDynamicSharedMemorySize, SM128);
    cudaFuncSetAttribute((const void*)gemm2<128, 1, false, true>,
                         cudaFuncAttributeMaxDynamicSharedMemorySize, SM128);

    const int T = 256;
    int gE = (E + T - 1) / T;
    int gW = (N + 7) / 8;
    int gGemm = (N + 127) / 128;
    int gApply = (N * 32 + T - 1) / T;
    int gScan = (N + 1023) / 1024;
    float invM = 1.0f / (float)N;

    prep_kernel<<<gApply, T>>>(x, ei + E, Wl0, Wr0, Wl1, Wr1, Wl2, Wr2, N * 32, E);
    scan_kernel<<<gScan, 1024>>>(N);
    scatter_kernel<<<gE, T>>>(ei, ei + E, ew, E);

    // ----- layer 0 -----
    layer_mid<false><<<gW, T>>>(x16, nullptr, nullptr, nullptr, invM, N, gW);
    gemm2<128, 2, true, false><<<gGemm, T, SM128>>>(mH, mL, xH, xL, BH, BL, b0,
                                                    nullptr, h16, stats0, N);

    // ----- layer 1 (fused bnapply + aggregate-with-BN, fp16 everywhere) -----
    layer_mid<true><<<gW + gApply, T>>>(h16, stats0, g0, be0, invM, N, gW);
    gemm2<128, 2, true, false><<<gGemm, T, SM128>>>(mH, mL, yH, yL, BH + 32768, BL + 32768, b1,
                                                    nullptr, h16, stats1, N);

    // ----- layer 2 (bnapply -> GEMM (fp32+fp16) -> final aggregate) -----
    bnapply_kernel<<<gApply, T>>>(stats1, g1, be1, invM, N * 32);
    gemm2<128, 1, false, true><<<gGemm, T, SM128>>>(nullptr, nullptr, yH, yL,
                                                    BH + 65536, BL + 65536, nullptr, h, h16, nullptr, N);
    agg_final<<<gW, T>>>(h, h16, b2, out, N);
}